// round 2
// baseline (speedup 1.0000x reference)
#include <cuda_runtime.h>
#include <math.h>

#define S_SRC 128
#define S_TGT 64
#define BATCH 32
#define EDIM  256
#define HDIM  512
#define VOCAB 32000
#define G4    (4*HDIM)   // 2048

// ---------------- scratch (static device allocations; no cudaMalloc) --------
__device__ float g_src_emb[S_SRC*BATCH*EDIM];     // [t][b][e]
__device__ float g_tgt_emb[S_TGT*BATCH*EDIM];     // [t][b][e]
__device__ float g_xih_f [S_SRC*BATCH*G4];        // x@Wih^T + b  (fwd enc), row = t*32+b
__device__ float g_xih_b [S_SRC*BATCH*G4];        // bwd enc (same row indexing by position)
__device__ float g_xihd  [S_TGT*BATCH*G4];        // decoder x_t part + dec bias
__device__ float g_enc_out [BATCH*S_SRC*2*HDIM];  // [b][s][1024]
__device__ float g_enc_proj[BATCH*S_SRC*HDIM];    // [b][s][512]
__device__ float g_hf[BATCH*HDIM];
__device__ float g_cf[BATCH*HDIM];
__device__ float g_hb[BATCH*HDIM];                // becomes decoder h
__device__ float g_cb[BATCH*HDIM];                // becomes decoder c
__device__ float g_gpf[4*BATCH*G4];               // enc fwd gate partials (split-K 4)
__device__ float g_gpb[4*BATCH*G4];               // enc bwd gate partials
__device__ float g_gpd[6*BATCH*G4];               // dec gate partials (4 ctx + 2 h)
__device__ float g_qpart[4*BATCH*HDIM];           // q partials (split-K 4)
__device__ float g_scores[BATCH*S_SRC];
__device__ float g_ctx[BATCH*2*HDIM];
__device__ float g_hs[S_TGT*BATCH*HDIM];          // decoder hiddens, row = t*32+b
__device__ float g_bef[G4];                        // bih+bhh combined biases
__device__ float g_beb[G4];
__device__ float g_bd [G4];

// ---------------- generic NT GEMM: C[m,n] = sum_k A[m,k]*B[n,k] (+bias[n]) ---
// blockIdx.z selects a K-chunk of length kLen; partial written at C + z*splitStride.
// REMAP: row r -> output offset (r%32)*S_TGT*VOCAB + (r/32)*VOCAB (b,t remap for logits).
template<int BM,int BN,int BK,int TM,int TN,bool REMAP>
__global__ __launch_bounds__((BM/TM)*(BN/TN))
void gemm_nt(const float* __restrict__ A, int lda,
             const float* __restrict__ B, int ldb,
             const float* __restrict__ bias,
             float* __restrict__ C, int ldc,
             int kLen, long splitStride)
{
    constexpr int THREADS = (BM/TM)*(BN/TN);
    __shared__ float As[BK][BM+4];
    __shared__ float Bs[BK][BN+4];

    const int tid = threadIdx.x;
    const int tx  = tid % (BN/TN);
    const int ty  = tid / (BN/TN);
    const long row0 = (long)blockIdx.y * BM;
    const long col0 = (long)blockIdx.x * BN;

    const float* Ap = A + row0*lda + (long)blockIdx.z*kLen;
    const float* Bp = B + col0*ldb + (long)blockIdx.z*kLen;
    float*       Cp = C + (long)blockIdx.z*splitStride;

    float acc[TM][TN];
    #pragma unroll
    for (int i=0;i<TM;i++)
        #pragma unroll
        for (int j=0;j<TN;j++) acc[i][j]=0.f;

    for (int kt=0; kt<kLen; kt+=BK) {
        #pragma unroll
        for (int i=0;i<(BM*BK)/(4*THREADS);i++){
            int lid = tid + i*THREADS;
            int m  = lid/(BK/4);
            int kq = lid%(BK/4);
            float4 v = *reinterpret_cast<const float4*>(Ap + (long)m*lda + kt + kq*4);
            As[kq*4+0][m]=v.x; As[kq*4+1][m]=v.y; As[kq*4+2][m]=v.z; As[kq*4+3][m]=v.w;
        }
        #pragma unroll
        for (int i=0;i<(BN*BK)/(4*THREADS);i++){
            int lid = tid + i*THREADS;
            int n  = lid/(BK/4);
            int kq = lid%(BK/4);
            float4 v = *reinterpret_cast<const float4*>(Bp + (long)n*ldb + kt + kq*4);
            Bs[kq*4+0][n]=v.x; Bs[kq*4+1][n]=v.y; Bs[kq*4+2][n]=v.z; Bs[kq*4+3][n]=v.w;
        }
        __syncthreads();
        #pragma unroll
        for (int k=0;k<BK;k++){
            float a[TM], bb[TN];
            if constexpr ((TM % 4) == 0) {
                #pragma unroll
                for (int i=0;i<TM/4;i++){
                    float4 v = *reinterpret_cast<const float4*>(&As[k][ty*TM + i*4]);
                    a[i*4]=v.x; a[i*4+1]=v.y; a[i*4+2]=v.z; a[i*4+3]=v.w;
                }
            } else {
                #pragma unroll
                for (int i=0;i<TM;i++) a[i]=As[k][ty*TM+i];
            }
            if constexpr ((TN % 4) == 0) {
                #pragma unroll
                for (int j=0;j<TN/4;j++){
                    float4 v = *reinterpret_cast<const float4*>(&Bs[k][tx*TN + j*4]);
                    bb[j*4]=v.x; bb[j*4+1]=v.y; bb[j*4+2]=v.z; bb[j*4+3]=v.w;
                }
            } else {
                #pragma unroll
                for (int j=0;j<TN;j++) bb[j]=Bs[k][tx*TN+j];
            }
            #pragma unroll
            for (int i=0;i<TM;i++)
                #pragma unroll
                for (int j=0;j<TN;j++) acc[i][j] += a[i]*bb[j];
        }
        __syncthreads();
    }

    #pragma unroll
    for (int i=0;i<TM;i++){
        long r = row0 + ty*TM + i;
        #pragma unroll
        for (int j=0;j<TN;j++){
            long n = col0 + tx*TN + j;
            float val = acc[i][j];
            if (bias) val += bias[n];
            if constexpr (REMAP) {
                long b = r & 31, t = r >> 5;
                Cp[(b*S_TGT + t)*(long)VOCAB + n] = val;
            } else {
                Cp[r*(long)ldc + n] = val;
            }
        }
    }
}

// ---------------- small kernels ---------------------------------------------
__global__ void prep_kernel(const float* bihf,const float* bhhf,
                            const float* bihb,const float* bhhb,
                            const float* bihd,const float* bhhd,
                            float* bef,float* beb,float* bd,
                            float* hf,float* cf,float* hb,float* cb)
{
    int i = blockIdx.x*blockDim.x + threadIdx.x;
    if (i < G4){ bef[i]=bihf[i]+bhhf[i]; beb[i]=bihb[i]+bhhb[i]; bd[i]=bihd[i]+bhhd[i]; }
    if (i < BATCH*HDIM){ hf[i]=0.f; cf[i]=0.f; hb[i]=0.f; cb[i]=0.f; }
}

// out[t][b][e] = emb[tok[b][t]][e]   (B*E = 8192 = 2^13)
__global__ void embed_kernel(const int* __restrict__ tok,
                             const float* __restrict__ emb,
                             float* __restrict__ out, int S)
{
    int idx = blockIdx.x*blockDim.x + threadIdx.x;
    int e = idx & 255;
    int b = (idx >> 8) & 31;
    int t = idx >> 13;
    if (t < S) {
        int tk = tok[b*S + t];
        out[idx] = emb[(long)tk*EDIM + e];
    }
}

__device__ __forceinline__ float sigf(float x){ return 1.f/(1.f+expf(-x)); }

// encoder gating for both directions; blockIdx.y = dir (0 fwd, 1 bwd)
__global__ void enc_gating(const float* __restrict__ xih_f, const float* __restrict__ xih_b,
                           const float* __restrict__ gpf,   const float* __restrict__ gpb,
                           float* hf, float* cf, float* hb, float* cb,
                           float* __restrict__ enc_out, int t)
{
    int dir = blockIdx.y;
    int idx = blockIdx.x*blockDim.x + threadIdx.x;   // 0..16383
    int b = idx >> 9, u = idx & 511;
    const float* xih = dir ? xih_b : xih_f;
    const float* gp  = dir ? gpb   : gpf;
    float* h = dir ? hb : hf;
    float* c = dir ? cb : cf;
    int pos = dir ? (S_SRC-1-t) : t;
    long row = (long)pos*BATCH + b;

    float g[4];
    #pragma unroll
    for (int gi=0; gi<4; gi++){
        int j = u + gi*HDIM;
        float v = xih[row*G4 + j];
        #pragma unroll
        for (int p=0;p<4;p++) v += gp[(long)(p*BATCH + b)*G4 + j];
        g[gi]=v;
    }
    float cn = sigf(g[1])*c[idx] + sigf(g[0])*tanhf(g[2]);
    float hn = sigf(g[3])*tanhf(cn);
    c[idx]=cn; h[idx]=hn;
    enc_out[((long)b*S_SRC + pos)*(2*HDIM) + dir*HDIM + u] = hn;
}

// scores[b][s] = sum_h v[h]*tanh(q[b][h] + enc_proj[b][s][h]); q = sum of 4 partials
__global__ void attn_scores(const float* __restrict__ qpart,
                            const float* __restrict__ enc_proj,
                            const float* __restrict__ v,
                            float* __restrict__ scores)
{
    int gid  = blockIdx.x*blockDim.x + threadIdx.x;
    int warp = gid >> 5;
    int lane = threadIdx.x & 31;
    int b = warp >> 7, s = warp & 127;
    const float* ep = enc_proj + ((long)b*S_SRC + s)*HDIM;
    float acc = 0.f;
    for (int h=lane; h<HDIM; h+=32){
        float q = qpart[b*HDIM+h] + qpart[BATCH*HDIM + b*HDIM+h]
                + qpart[2*BATCH*HDIM + b*HDIM+h] + qpart[3*BATCH*HDIM + b*HDIM+h];
        acc += v[h]*tanhf(q + ep[h]);
    }
    #pragma unroll
    for (int o=16;o;o>>=1) acc += __shfl_xor_sync(0xffffffffu, acc, o);
    if (lane==0) scores[warp]=acc;
}

// softmax over s then context[b][d] = sum_s attw[s]*enc_out[b][s][d]
__global__ void softmax_ctx(const float* __restrict__ scores,
                            const float* __restrict__ enc_out,
                            float* __restrict__ ctx)
{
    int b = blockIdx.x;
    int tid = threadIdx.x;   // 256
    __shared__ float sw[S_SRC];
    __shared__ float red[S_SRC];
    float sc = (tid < S_SRC) ? scores[b*S_SRC + tid] : -1e30f;
    if (tid < S_SRC) red[tid] = sc;
    __syncthreads();
    for (int o=64;o>0;o>>=1){ if (tid<o) red[tid]=fmaxf(red[tid],red[tid+o]); __syncthreads(); }
    float mx = red[0];
    __syncthreads();
    float e = (tid < S_SRC) ? expf(sc-mx) : 0.f;
    if (tid < S_SRC) red[tid]=e;
    __syncthreads();
    for (int o=64;o>0;o>>=1){ if (tid<o) red[tid]+=red[tid+o]; __syncthreads(); }
    float inv = 1.f/red[0];
    if (tid < S_SRC) sw[tid] = e*inv;
    __syncthreads();
    const float* eo = enc_out + (long)b*S_SRC*(2*HDIM);
    for (int d=tid; d<2*HDIM; d+=256){
        float acc=0.f;
        #pragma unroll 8
        for (int s=0;s<S_SRC;s++) acc += sw[s]*eo[(long)s*(2*HDIM) + d];
        ctx[b*(2*HDIM)+d]=acc;
    }
}

// decoder gating: sums xihd (has bias) + 6 partials, LSTM update, stores h into hs
__global__ void dec_gating(const float* __restrict__ xihd, const float* __restrict__ gpd,
                           float* h, float* c, float* __restrict__ hs, int t)
{
    int idx = blockIdx.x*blockDim.x + threadIdx.x;  // 0..16383
    int b = idx >> 9, u = idx & 511;
    long row = (long)t*BATCH + b;
    float g[4];
    #pragma unroll
    for (int gi=0; gi<4; gi++){
        int j = u + gi*HDIM;
        float v = xihd[row*G4 + j];
        #pragma unroll
        for (int p=0;p<6;p++) v += gpd[(long)(p*BATCH + b)*G4 + j];
        g[gi]=v;
    }
    float cn = sigf(g[1])*c[idx] + sigf(g[0])*tanhf(g[2]);
    float hn = sigf(g[3])*tanhf(cn);
    c[idx]=cn; h[idx]=hn;
    hs[row*HDIM + u] = hn;
}

// ---------------- driver -----------------------------------------------------
extern "C" void kernel_launch(void* const* d_in, const int* in_sizes, int n_in,
                              void* d_out, int out_size)
{
    (void)in_sizes; (void)n_in; (void)out_size;
    const int*   src   = (const int*)  d_in[0];
    const int*   tgt   = (const int*)  d_in[1];
    const float* emb   = (const float*)d_in[2];
    const float* eWih_f= (const float*)d_in[3];
    const float* eWhh_f= (const float*)d_in[4];
    const float* ebih_f= (const float*)d_in[5];
    const float* ebhh_f= (const float*)d_in[6];
    const float* eWih_b= (const float*)d_in[7];
    const float* eWhh_b= (const float*)d_in[8];
    const float* ebih_b= (const float*)d_in[9];
    const float* ebhh_b= (const float*)d_in[10];
    const float* dWih  = (const float*)d_in[11];
    const float* dWhh  = (const float*)d_in[12];
    const float* dbih  = (const float*)d_in[13];
    const float* dbhh  = (const float*)d_in[14];
    const float* attW  = (const float*)d_in[15];
    const float* attB  = (const float*)d_in[16];
    const float* vvec  = (const float*)d_in[17];
    const float* outW  = (const float*)d_in[18];
    const float* outB  = (const float*)d_in[19];
    float* out = (float*)d_out;

    float *src_emb,*tgt_emb,*xih_f,*xih_b,*xihd,*enc_out,*enc_proj;
    float *hf,*cf,*hb,*cb,*gpf,*gpb,*gpd,*qpart,*scores,*ctx,*hs,*bef,*beb,*bd;
    cudaGetSymbolAddress((void**)&src_emb,  g_src_emb);
    cudaGetSymbolAddress((void**)&tgt_emb,  g_tgt_emb);
    cudaGetSymbolAddress((void**)&xih_f,    g_xih_f);
    cudaGetSymbolAddress((void**)&xih_b,    g_xih_b);
    cudaGetSymbolAddress((void**)&xihd,     g_xihd);
    cudaGetSymbolAddress((void**)&enc_out,  g_enc_out);
    cudaGetSymbolAddress((void**)&enc_proj, g_enc_proj);
    cudaGetSymbolAddress((void**)&hf, g_hf);
    cudaGetSymbolAddress((void**)&cf, g_cf);
    cudaGetSymbolAddress((void**)&hb, g_hb);
    cudaGetSymbolAddress((void**)&cb, g_cb);
    cudaGetSymbolAddress((void**)&gpf, g_gpf);
    cudaGetSymbolAddress((void**)&gpb, g_gpb);
    cudaGetSymbolAddress((void**)&gpd, g_gpd);
    cudaGetSymbolAddress((void**)&qpart, g_qpart);
    cudaGetSymbolAddress((void**)&scores, g_scores);
    cudaGetSymbolAddress((void**)&ctx, g_ctx);
    cudaGetSymbolAddress((void**)&hs, g_hs);
    cudaGetSymbolAddress((void**)&bef, g_bef);
    cudaGetSymbolAddress((void**)&beb, g_beb);
    cudaGetSymbolAddress((void**)&bd,  g_bd);

    // phase 0: biases + zero states + embeddings
    prep_kernel<<<64,256>>>(ebih_f,ebhh_f,ebih_b,ebhh_b,dbih,dbhh,bef,beb,bd,hf,cf,hb,cb);
    embed_kernel<<<(S_SRC*BATCH*EDIM)/256,256>>>(src, emb, src_emb, S_SRC);
    embed_kernel<<<(S_TGT*BATCH*EDIM)/256,256>>>(tgt, emb, tgt_emb, S_TGT);

    // phase 1: time-parallel input GEMMs (xih + bias)
    gemm_nt<128,64,16,8,4,false><<<dim3(G4/64, (S_SRC*BATCH)/128, 1),256>>>(
        src_emb, EDIM, eWih_f, EDIM, bef, xih_f, G4, EDIM, 0);
    gemm_nt<128,64,16,8,4,false><<<dim3(G4/64, (S_SRC*BATCH)/128, 1),256>>>(
        src_emb, EDIM, eWih_b, EDIM, beb, xih_b, G4, EDIM, 0);
    gemm_nt<128,64,16,8,4,false><<<dim3(G4/64, (S_TGT*BATCH)/128, 1),256>>>(
        tgt_emb, EDIM, dWih, EDIM + 2*HDIM, bd, xihd, G4, EDIM, 0);

    // phase 2: encoder recurrence (fwd & bwd per step; split-K=4 recurrent GEMMs)
    for (int t=0; t<S_SRC; t++){
        gemm_nt<32,64,32,2,4,false><<<dim3(G4/64,1,4),256>>>(
            hf, HDIM, eWhh_f, HDIM, nullptr, gpf, G4, HDIM/4, (long)BATCH*G4);
        gemm_nt<32,64,32,2,4,false><<<dim3(G4/64,1,4),256>>>(
            hb, HDIM, eWhh_b, HDIM, nullptr, gpb, G4, HDIM/4, (long)BATCH*G4);
        enc_gating<<<dim3(64,2),256>>>(xih_f, xih_b, gpf, gpb, hf, cf, hb, cb, enc_out, t);
    }

    // phase 3: enc_proj = enc_out @ We^T + att_b   (We = attW cols [512:1536))
    gemm_nt<128,64,16,8,4,false><<<dim3(HDIM/64, (BATCH*S_SRC)/128, 1),256>>>(
        enc_out, 2*HDIM, attW + HDIM, 3*HDIM, attB, enc_proj, HDIM, 2*HDIM, 0);

    // phase 4: decoder recurrence (h,c start as backward-encoder finals in hb,cb)
    for (int t=0; t<S_TGT; t++){
        // q = h @ Wq^T  (Wq = attW cols [0:512)), split-K=4
        gemm_nt<32,64,32,2,4,false><<<dim3(HDIM/64,1,4),256>>>(
            hb, HDIM, attW, 3*HDIM, nullptr, qpart, HDIM, HDIM/4, (long)BATCH*HDIM);
        attn_scores<<<(BATCH*S_SRC)/8,256>>>(qpart, enc_proj, vvec, scores);
        softmax_ctx<<<BATCH,256>>>(scores, enc_out, ctx);
        // gates: ctx @ Wih_ctx^T (cols [256:1280), split-K=4) + h @ Whh^T (split-K=2)
        gemm_nt<32,64,32,2,4,false><<<dim3(G4/64,1,4),256>>>(
            ctx, 2*HDIM, dWih + EDIM, EDIM + 2*HDIM, nullptr, gpd, G4, (2*HDIM)/4, (long)BATCH*G4);
        gemm_nt<32,64,32,2,4,false><<<dim3(G4/64,1,2),256>>>(
            hb, HDIM, dWhh, HDIM, nullptr, gpd + (long)4*BATCH*G4, G4, HDIM/2, (long)BATCH*G4);
        dec_gating<<<64,256>>>(xihd, gpd, hb, cb, hs, t);
    }

    // phase 5: one big logits GEMM for all timesteps, with (t,b)->(b,t) remap
    gemm_nt<128,64,16,8,4,true><<<dim3(VOCAB/64, (S_TGT*BATCH)/128, 1),256>>>(
        hs, HDIM, outW, HDIM, outB, out, VOCAB, HDIM, 0);
}

// round 4
// speedup vs baseline: 1.0019x; 1.0019x over previous
#include <cuda_runtime.h>
#include <math.h>

#define S_SRC 128
#define S_TGT 64
#define BATCH 32
#define EDIM  256
#define HDIM  512
#define VOCAB 32000
#define G4    (4*HDIM)   // 2048

// ---------------- scratch (static device allocations; no cudaMalloc) --------
__device__ float g_src_emb[S_SRC*BATCH*EDIM];     // [t][b][e]
__device__ float g_tgt_emb[S_TGT*BATCH*EDIM];     // [t][b][e]
__device__ float g_xih_f [S_SRC*BATCH*G4];        // x@Wih^T + b  (fwd enc), row = t*32+b
__device__ float g_xih_b [S_SRC*BATCH*G4];        // bwd enc (same row indexing by position)
__device__ float g_xihd  [S_TGT*BATCH*G4];        // decoder x_t part + dec bias
__device__ float g_enc_out [BATCH*S_SRC*2*HDIM];  // [b][s][1024]
__device__ float g_enc_proj[BATCH*S_SRC*HDIM];    // [b][s][512]
__device__ float g_hf[BATCH*HDIM];
__device__ float g_cf[BATCH*HDIM];
__device__ float g_hb[BATCH*HDIM];                // becomes decoder h
__device__ float g_cb[BATCH*HDIM];                // becomes decoder c
__device__ float g_gpf[4*BATCH*G4];               // enc fwd gate partials (split-K 4)
__device__ float g_gpb[4*BATCH*G4];               // enc bwd gate partials
__device__ float g_gpd[6*BATCH*G4];               // dec gate partials (4 ctx + 2 h)
__device__ float g_qpart[4*BATCH*HDIM];           // q partials (split-K 4)
__device__ float g_scores[BATCH*S_SRC];
__device__ float g_ctx[BATCH*2*HDIM];
__device__ float g_hs[S_TGT*BATCH*HDIM];          // decoder hiddens, row = t*32+b
__device__ float g_bef[G4];                        // bih+bhh combined biases
__device__ float g_beb[G4];
__device__ float g_bd [G4];

// ---------------- generic NT GEMM: C[m,n] = sum_k A[m,k]*B[n,k] (+bias[n]) ---
// blockIdx.z selects a K-chunk of length kLen; partial written at C + z*splitStride.
// REMAP: row r -> output offset (r%32)*S_TGT*VOCAB + (r/32)*VOCAB (b,t remap for logits).
template<int BM,int BN,int BK,int TM,int TN,bool REMAP>
__global__ __launch_bounds__((BM/TM)*(BN/TN))
void gemm_nt(const float* __restrict__ A, int lda,
             const float* __restrict__ B, int ldb,
             const float* __restrict__ bias,
             float* __restrict__ C, int ldc,
             int kLen, long splitStride)
{
    constexpr int THREADS = (BM/TM)*(BN/TN);
    __shared__ float As[BK][BM+4];
    __shared__ float Bs[BK][BN+4];

    const int tid = threadIdx.x;
    const int tx  = tid % (BN/TN);
    const int ty  = tid / (BN/TN);
    const long row0 = (long)blockIdx.y * BM;
    const long col0 = (long)blockIdx.x * BN;

    const float* Ap = A + row0*lda + (long)blockIdx.z*kLen;
    const float* Bp = B + col0*ldb + (long)blockIdx.z*kLen;
    float*       Cp = C + (long)blockIdx.z*splitStride;

    float acc[TM][TN];
    #pragma unroll
    for (int i=0;i<TM;i++)
        #pragma unroll
        for (int j=0;j<TN;j++) acc[i][j]=0.f;

    for (int kt=0; kt<kLen; kt+=BK) {
        #pragma unroll
        for (int i=0;i<(BM*BK)/(4*THREADS);i++){
            int lid = tid + i*THREADS;
            int m  = lid/(BK/4);
            int kq = lid%(BK/4);
            float4 v = *reinterpret_cast<const float4*>(Ap + (long)m*lda + kt + kq*4);
            As[kq*4+0][m]=v.x; As[kq*4+1][m]=v.y; As[kq*4+2][m]=v.z; As[kq*4+3][m]=v.w;
        }
        #pragma unroll
        for (int i=0;i<(BN*BK)/(4*THREADS);i++){
            int lid = tid + i*THREADS;
            int n  = lid/(BK/4);
            int kq = lid%(BK/4);
            float4 v = *reinterpret_cast<const float4*>(Bp + (long)n*ldb + kt + kq*4);
            Bs[kq*4+0][n]=v.x; Bs[kq*4+1][n]=v.y; Bs[kq*4+2][n]=v.z; Bs[kq*4+3][n]=v.w;
        }
        __syncthreads();
        #pragma unroll
        for (int k=0;k<BK;k++){
            float a[TM], bb[TN];
            if constexpr ((TM % 4) == 0) {
                #pragma unroll
                for (int i=0;i<TM/4;i++){
                    float4 v = *reinterpret_cast<const float4*>(&As[k][ty*TM + i*4]);
                    a[i*4]=v.x; a[i*4+1]=v.y; a[i*4+2]=v.z; a[i*4+3]=v.w;
                }
            } else {
                #pragma unroll
                for (int i=0;i<TM;i++) a[i]=As[k][ty*TM+i];
            }
            if constexpr ((TN % 4) == 0) {
                #pragma unroll
                for (int j=0;j<TN/4;j++){
                    float4 v = *reinterpret_cast<const float4*>(&Bs[k][tx*TN + j*4]);
                    bb[j*4]=v.x; bb[j*4+1]=v.y; bb[j*4+2]=v.z; bb[j*4+3]=v.w;
                }
            } else {
                #pragma unroll
                for (int j=0;j<TN;j++) bb[j]=Bs[k][tx*TN+j];
            }
            #pragma unroll
            for (int i=0;i<TM;i++)
                #pragma unroll
                for (int j=0;j<TN;j++) acc[i][j] += a[i]*bb[j];
        }
        __syncthreads();
    }

    #pragma unroll
    for (int i=0;i<TM;i++){
        long r = row0 + ty*TM + i;
        #pragma unroll
        for (int j=0;j<TN;j++){
            long n = col0 + tx*TN + j;
            float val = acc[i][j];
            if (bias) val += bias[n];
            if constexpr (REMAP) {
                long b = r & 31, t = r >> 5;
                Cp[(b*S_TGT + t)*(long)VOCAB + n] = val;
            } else {
                Cp[r*(long)ldc + n] = val;
            }
        }
    }
}

// ---------------- small kernels ---------------------------------------------
__global__ void prep_kernel(const float* bihf,const float* bhhf,
                            const float* bihb,const float* bhhb,
                            const float* bihd,const float* bhhd,
                            float* bef,float* beb,float* bd,
                            float* hf,float* cf,float* hb,float* cb)
{
    int i = blockIdx.x*blockDim.x + threadIdx.x;
    if (i < G4){ bef[i]=bihf[i]+bhhf[i]; beb[i]=bihb[i]+bhhb[i]; bd[i]=bihd[i]+bhhd[i]; }
    if (i < BATCH*HDIM){ hf[i]=0.f; cf[i]=0.f; hb[i]=0.f; cb[i]=0.f; }
}

// out[t][b][e] = emb[tok[b][t]][e]   (B*E = 8192 = 2^13)
__global__ void embed_kernel(const int* __restrict__ tok,
                             const float* __restrict__ emb,
                             float* __restrict__ out, int S)
{
    int idx = blockIdx.x*blockDim.x + threadIdx.x;
    int e = idx & 255;
    int b = (idx >> 8) & 31;
    int t = idx >> 13;
    if (t < S) {
        int tk = tok[b*S + t];
        out[idx] = emb[(long)tk*EDIM + e];
    }
}

__device__ __forceinline__ float sigf(float x){ return 1.f/(1.f+expf(-x)); }

// encoder gating for both directions; blockIdx.y = dir (0 fwd, 1 bwd)
__global__ void enc_gating(const float* __restrict__ xih_f, const float* __restrict__ xih_b,
                           const float* __restrict__ gpf,   const float* __restrict__ gpb,
                           float* hf, float* cf, float* hb, float* cb,
                           float* __restrict__ enc_out, int t)
{
    int dir = blockIdx.y;
    int idx = blockIdx.x*blockDim.x + threadIdx.x;   // 0..16383
    int b = idx >> 9, u = idx & 511;
    const float* xih = dir ? xih_b : xih_f;
    const float* gp  = dir ? gpb   : gpf;
    float* h = dir ? hb : hf;
    float* c = dir ? cb : cf;
    int pos = dir ? (S_SRC-1-t) : t;
    long row = (long)pos*BATCH + b;

    float g[4];
    #pragma unroll
    for (int gi=0; gi<4; gi++){
        int j = u + gi*HDIM;
        float v = xih[row*G4 + j];
        #pragma unroll
        for (int p=0;p<4;p++) v += gp[(long)(p*BATCH + b)*G4 + j];
        g[gi]=v;
    }
    float cn = sigf(g[1])*c[idx] + sigf(g[0])*tanhf(g[2]);
    float hn = sigf(g[3])*tanhf(cn);
    c[idx]=cn; h[idx]=hn;
    enc_out[((long)b*S_SRC + pos)*(2*HDIM) + dir*HDIM + u] = hn;
}

// scores[b][s] = sum_h v[h]*tanh(q[b][h] + enc_proj[b][s][h]); q = sum of 4 partials
__global__ void attn_scores(const float* __restrict__ qpart,
                            const float* __restrict__ enc_proj,
                            const float* __restrict__ v,
                            float* __restrict__ scores)
{
    int gid  = blockIdx.x*blockDim.x + threadIdx.x;
    int warp = gid >> 5;
    int lane = threadIdx.x & 31;
    int b = warp >> 7, s = warp & 127;
    const float* ep = enc_proj + ((long)b*S_SRC + s)*HDIM;
    float acc = 0.f;
    for (int h=lane; h<HDIM; h+=32){
        float q = qpart[b*HDIM+h] + qpart[BATCH*HDIM + b*HDIM+h]
                + qpart[2*BATCH*HDIM + b*HDIM+h] + qpart[3*BATCH*HDIM + b*HDIM+h];
        acc += v[h]*tanhf(q + ep[h]);
    }
    #pragma unroll
    for (int o=16;o;o>>=1) acc += __shfl_xor_sync(0xffffffffu, acc, o);
    if (lane==0) scores[warp]=acc;
}

// softmax over s then context[b][d] = sum_s attw[s]*enc_out[b][s][d]
__global__ void softmax_ctx(const float* __restrict__ scores,
                            const float* __restrict__ enc_out,
                            float* __restrict__ ctx)
{
    int b = blockIdx.x;
    int tid = threadIdx.x;   // 256
    __shared__ float sw[S_SRC];
    __shared__ float red[S_SRC];
    float sc = (tid < S_SRC) ? scores[b*S_SRC + tid] : -1e30f;
    if (tid < S_SRC) red[tid] = sc;
    __syncthreads();
    for (int o=64;o>0;o>>=1){ if (tid<o) red[tid]=fmaxf(red[tid],red[tid+o]); __syncthreads(); }
    float mx = red[0];
    __syncthreads();
    float e = (tid < S_SRC) ? expf(sc-mx) : 0.f;
    if (tid < S_SRC) red[tid]=e;
    __syncthreads();
    for (int o=64;o>0;o>>=1){ if (tid<o) red[tid]+=red[tid+o]; __syncthreads(); }
    float inv = 1.f/red[0];
    if (tid < S_SRC) sw[tid] = e*inv;
    __syncthreads();
    const float* eo = enc_out + (long)b*S_SRC*(2*HDIM);
    for (int d=tid; d<2*HDIM; d+=256){
        float acc=0.f;
        #pragma unroll 8
        for (int s=0;s<S_SRC;s++) acc += sw[s]*eo[(long)s*(2*HDIM) + d];
        ctx[b*(2*HDIM)+d]=acc;
    }
}

// decoder gating: sums xihd (has bias) + 6 partials, LSTM update, stores h into hs
__global__ void dec_gating(const float* __restrict__ xihd, const float* __restrict__ gpd,
                           float* h, float* c, float* __restrict__ hs, int t)
{
    int idx = blockIdx.x*blockDim.x + threadIdx.x;  // 0..16383
    int b = idx >> 9, u = idx & 511;
    long row = (long)t*BATCH + b;
    float g[4];
    #pragma unroll
    for (int gi=0; gi<4; gi++){
        int j = u + gi*HDIM;
        float v = xihd[row*G4 + j];
        #pragma unroll
        for (int p=0;p<6;p++) v += gpd[(long)(p*BATCH + b)*G4 + j];
        g[gi]=v;
    }
    float cn = sigf(g[1])*c[idx] + sigf(g[0])*tanhf(g[2]);
    float hn = sigf(g[3])*tanhf(cn);
    c[idx]=cn; h[idx]=hn;
    hs[row*HDIM + u] = hn;
}

// ---------------- driver -----------------------------------------------------
extern "C" void kernel_launch(void* const* d_in, const int* in_sizes, int n_in,
                              void* d_out, int out_size)
{
    (void)in_sizes; (void)n_in; (void)out_size;
    const int*   src   = (const int*)  d_in[0];
    const int*   tgt   = (const int*)  d_in[1];
    const float* emb   = (const float*)d_in[2];
    const float* eWih_f= (const float*)d_in[3];
    const float* eWhh_f= (const float*)d_in[4];
    const float* ebih_f= (const float*)d_in[5];
    const float* ebhh_f= (const float*)d_in[6];
    const float* eWih_b= (const float*)d_in[7];
    const float* eWhh_b= (const float*)d_in[8];
    const float* ebih_b= (const float*)d_in[9];
    const float* ebhh_b= (const float*)d_in[10];
    const float* dWih  = (const float*)d_in[11];
    const float* dWhh  = (const float*)d_in[12];
    const float* dbih  = (const float*)d_in[13];
    const float* dbhh  = (const float*)d_in[14];
    const float* attW  = (const float*)d_in[15];
    const float* attB  = (const float*)d_in[16];
    const float* vvec  = (const float*)d_in[17];
    const float* outW  = (const float*)d_in[18];
    const float* outB  = (const float*)d_in[19];
    float* out = (float*)d_out;

    float *src_emb,*tgt_emb,*xih_f,*xih_b,*xihd,*enc_out,*enc_proj;
    float *hf,*cf,*hb,*cb,*gpf,*gpb,*gpd,*qpart,*scores,*ctx,*hs,*bef,*beb,*bd;
    cudaGetSymbolAddress((void**)&src_emb,  g_src_emb);
    cudaGetSymbolAddress((void**)&tgt_emb,  g_tgt_emb);
    cudaGetSymbolAddress((void**)&xih_f,    g_xih_f);
    cudaGetSymbolAddress((void**)&xih_b,    g_xih_b);
    cudaGetSymbolAddress((void**)&xihd,     g_xihd);
    cudaGetSymbolAddress((void**)&enc_out,  g_enc_out);
    cudaGetSymbolAddress((void**)&enc_proj, g_enc_proj);
    cudaGetSymbolAddress((void**)&hf, g_hf);
    cudaGetSymbolAddress((void**)&cf, g_cf);
    cudaGetSymbolAddress((void**)&hb, g_hb);
    cudaGetSymbolAddress((void**)&cb, g_cb);
    cudaGetSymbolAddress((void**)&gpf, g_gpf);
    cudaGetSymbolAddress((void**)&gpb, g_gpb);
    cudaGetSymbolAddress((void**)&gpd, g_gpd);
    cudaGetSymbolAddress((void**)&qpart, g_qpart);
    cudaGetSymbolAddress((void**)&scores, g_scores);
    cudaGetSymbolAddress((void**)&ctx, g_ctx);
    cudaGetSymbolAddress((void**)&hs, g_hs);
    cudaGetSymbolAddress((void**)&bef, g_bef);
    cudaGetSymbolAddress((void**)&beb, g_beb);
    cudaGetSymbolAddress((void**)&bd,  g_bd);

    // phase 0: biases + zero states + embeddings
    prep_kernel<<<64,256>>>(ebih_f,ebhh_f,ebih_b,ebhh_b,dbih,dbhh,bef,beb,bd,hf,cf,hb,cb);
    embed_kernel<<<(S_SRC*BATCH*EDIM)/256,256>>>(src, emb, src_emb, S_SRC);
    embed_kernel<<<(S_TGT*BATCH*EDIM)/256,256>>>(tgt, emb, tgt_emb, S_TGT);

    // phase 1: time-parallel input GEMMs (xih + bias)
    gemm_nt<128,64,16,8,4,false><<<dim3(G4/64, (S_SRC*BATCH)/128, 1),256>>>(
        src_emb, EDIM, eWih_f, EDIM, bef, xih_f, G4, EDIM, 0);
    gemm_nt<128,64,16,8,4,false><<<dim3(G4/64, (S_SRC*BATCH)/128, 1),256>>>(
        src_emb, EDIM, eWih_b, EDIM, beb, xih_b, G4, EDIM, 0);
    gemm_nt<128,64,16,8,4,false><<<dim3(G4/64, (S_TGT*BATCH)/128, 1),256>>>(
        tgt_emb, EDIM, dWih, EDIM + 2*HDIM, bd, xihd, G4, EDIM, 0);

    // phase 2: encoder recurrence (fwd & bwd per step; split-K=4 recurrent GEMMs)
    for (int t=0; t<S_SRC; t++){
        gemm_nt<32,64,32,2,4,false><<<dim3(G4/64,1,4),256>>>(
            hf, HDIM, eWhh_f, HDIM, nullptr, gpf, G4, HDIM/4, (long)BATCH*G4);
        gemm_nt<32,64,32,2,4,false><<<dim3(G4/64,1,4),256>>>(
            hb, HDIM, eWhh_b, HDIM, nullptr, gpb, G4, HDIM/4, (long)BATCH*G4);
        enc_gating<<<dim3(64,2),256>>>(xih_f, xih_b, gpf, gpb, hf, cf, hb, cb, enc_out, t);
    }

    // phase 3: enc_proj = enc_out @ We^T + att_b   (We = attW cols [512:1536))
    gemm_nt<128,64,16,8,4,false><<<dim3(HDIM/64, (BATCH*S_SRC)/128, 1),256>>>(
        enc_out, 2*HDIM, attW + HDIM, 3*HDIM, attB, enc_proj, HDIM, 2*HDIM, 0);

    // phase 4: decoder recurrence (h,c start as backward-encoder finals in hb,cb)
    for (int t=0; t<S_TGT; t++){
        // q = h @ Wq^T  (Wq = attW cols [0:512)), split-K=4
        gemm_nt<32,64,32,2,4,false><<<dim3(HDIM/64,1,4),256>>>(
            hb, HDIM, attW, 3*HDIM, nullptr, qpart, HDIM, HDIM/4, (long)BATCH*HDIM);
        attn_scores<<<(BATCH*S_SRC)/8,256>>>(qpart, enc_proj, vvec, scores);
        softmax_ctx<<<BATCH,256>>>(scores, enc_out, ctx);
        // gates: ctx @ Wih_ctx^T (cols [256:1280), split-K=4) + h @ Whh^T (split-K=2)
        gemm_nt<32,64,32,2,4,false><<<dim3(G4/64,1,4),256>>>(
            ctx, 2*HDIM, dWih + EDIM, EDIM + 2*HDIM, nullptr, gpd, G4, (2*HDIM)/4, (long)BATCH*G4);
        gemm_nt<32,64,32,2,4,false><<<dim3(G4/64,1,2),256>>>(
            hb, HDIM, dWhh, HDIM, nullptr, gpd + (long)4*BATCH*G4, G4, HDIM/2, (long)BATCH*G4);
        dec_gating<<<64,256>>>(xihd, gpd, hb, cb, hs, t);
    }

    // phase 5: one big logits GEMM for all timesteps, with (t,b)->(b,t) remap
    gemm_nt<128,64,16,8,4,true><<<dim3(VOCAB/64, (S_TGT*BATCH)/128, 1),256>>>(
        hs, HDIM, outW, HDIM, outB, out, VOCAB, HDIM, 0);
}